// round 1
// baseline (speedup 1.0000x reference)
#include <cuda_runtime.h>

// Problem constants
#define cB 16
#define cT 16
#define cN 184
#define cD 128
#define cH 8
#define cHD 16
#define cEMB 10

// Device scratch (allocation-free requirement -> __device__ globals)
static __device__ float gXmid[cB * cT * cN * cD];   // pre-Wo intermediate [B,T,N,128]
static __device__ float gAdpRaw[cN * cN];
static __device__ float gAdpRow[cN * cN];           // softmax(adp, axis=-1)
static __device__ float gAdpColT[cN * cN];          // gAdpColT[i][k] = softmax(adp, axis=0)[k][i]

// Shared-memory strides / offsets (floats)
#define S_ST 185     // 184x185 score matrix (conflict-free rows AND columns)
#define V_ST 20      // q/k/v tiles 184x16 padded to 20 (conflict-free float4 column-ish access)
#define IN_ST 132    // staged input slice 184x132
#define W_ST 132     // weight rows 16x132

#define OFF_S   0
#define OFF_Q   34040                 // 184*185
#define OFF_K   (OFF_Q + 3680)       // 184*20
#define OFF_V   (OFF_K + 3680)
#define OFF_W   (OFF_V + 3680)       // wq,wk,wv : 3 * 16*132 = 6336
#define OFF_WM  (OFF_W + 6336)       // 16*64
#define OFF_O   (OFF_WM + 1024)      // 184*16
#define OFF_B   (OFF_O + 2944)       // bq,bk,bv,bm slices (16 each)
#define OFF_RM  (OFF_B + 64)
#define OFF_CM  (OFF_RM + 184)
#define FUSED_FLOATS (OFF_CM + 184)  // 55816 floats = 223264 bytes

#define PROJ_FLOATS (128 * 133 + 32 * 133 + 128)   // 21408 floats = 85632 bytes

// ---------------------------------------------------------------------------
// adp = ne1 @ ne2 ; row softmax
// ---------------------------------------------------------------------------
__global__ void adp_row_kernel(const float* __restrict__ ne1,
                               const float* __restrict__ ne2)
{
    __shared__ float red[256];
    const int i = blockIdx.x;       // row of adp
    const int j = threadIdx.x;

    float val = -1e30f;
    if (j < cN) {
        float acc = 0.f;
#pragma unroll
        for (int e = 0; e < cEMB; e++) acc += ne1[i * cEMB + e] * ne2[e * cN + j];
        val = acc;
        gAdpRaw[i * cN + j] = acc;
    }
    red[j] = val;
    __syncthreads();
    for (int s = 128; s > 0; s >>= 1) {
        if (j < s) red[j] = fmaxf(red[j], red[j + s]);
        __syncthreads();
    }
    const float m = red[0];
    __syncthreads();
    const float e = (j < cN) ? __expf(val - m) : 0.f;
    red[j] = e;
    __syncthreads();
    for (int s = 128; s > 0; s >>= 1) {
        if (j < s) red[j] += red[j + s];
        __syncthreads();
    }
    const float inv = 1.f / red[0];
    if (j < cN) gAdpRow[i * cN + j] = e * inv;
}

// column softmax of adp, stored transposed: gAdpColT[i][k] = adp_col[k][i]
__global__ void adp_col_kernel()
{
    __shared__ float red[256];
    const int i = blockIdx.x;       // column of adp
    const int k = threadIdx.x;

    float val = -1e30f;
    if (k < cN) val = gAdpRaw[k * cN + i];
    red[k] = val;
    __syncthreads();
    for (int s = 128; s > 0; s >>= 1) {
        if (k < s) red[k] = fmaxf(red[k], red[k + s]);
        __syncthreads();
    }
    const float m = red[0];
    __syncthreads();
    const float e = (k < cN) ? __expf(val - m) : 0.f;
    red[k] = e;
    __syncthreads();
    for (int s = 128; s > 0; s >>= 1) {
        if (k < s) red[k] += red[k + s];
        __syncthreads();
    }
    const float inv = 1.f / red[0];
    if (k < cN) gAdpColT[i * cN + k] = e * inv;
}

// ---------------------------------------------------------------------------
// Helpers for the fused kernel
// ---------------------------------------------------------------------------
__device__ __forceinline__ void fold_wm(const float* acc, const float* sWM, int off,
                                        float* sO, int i, bool first, const float* sBm)
{
#pragma unroll
    for (int jj = 0; jj < cHD; jj++) {
        const float4* w4 = (const float4*)(sWM + jj * 64 + off);
        float o = first ? sBm[jj] : sO[i * cHD + jj];
#pragma unroll
        for (int f4 = 0; f4 < 4; f4++) {
            float4 w = w4[f4];
            o += acc[4 * f4 + 0] * w.x + acc[4 * f4 + 1] * w.y +
                 acc[4 * f4 + 2] * w.z + acc[4 * f4 + 3] * w.w;
        }
        sO[i * cHD + jj] = o;
    }
}

__device__ __forceinline__ void mat_row_dot(const float* sM, const float* sVv,
                                            int i, float* acc)
{
#pragma unroll
    for (int f = 0; f < cHD; f++) acc[f] = 0.f;
    for (int k = 0; k < cN; k++) {
        const float a = sM[i * S_ST + k];
        const float4* vr = (const float4*)(sVv + k * V_ST);
#pragma unroll
        for (int f4 = 0; f4 < 4; f4++) {
            float4 v4 = vr[f4];
            acc[4 * f4 + 0] += a * v4.x; acc[4 * f4 + 1] += a * v4.y;
            acc[4 * f4 + 2] += a * v4.z; acc[4 * f4 + 3] += a * v4.w;
        }
    }
}

// ---------------------------------------------------------------------------
// Fused per-(b,t,h) kernel: projections + dual-softmax attention + adp mixes + Wm
// ---------------------------------------------------------------------------
__global__ void __launch_bounds__(256, 1)
fused_kernel(const float* __restrict__ gq, const float* __restrict__ gk,
             const float* __restrict__ gv,
             const float* __restrict__ Wq, const float* __restrict__ bq,
             const float* __restrict__ Wk, const float* __restrict__ bk,
             const float* __restrict__ Wv, const float* __restrict__ bv,
             const float* __restrict__ Wm, const float* __restrict__ bm)
{
    extern __shared__ float sm[];
    float* sS  = sm + OFF_S;
    float* sQ  = sm + OFF_Q;
    float* sK  = sm + OFF_K;
    float* sV  = sm + OFF_V;
    float* sW  = sm + OFF_W;
    float* sWM = sm + OFF_WM;
    float* sO  = sm + OFF_O;
    float* sB  = sm + OFF_B;
    float* sRM = sm + OFF_RM;
    float* sCM = sm + OFF_CM;

    const int tid = threadIdx.x;
    const int bt = blockIdx.x >> 3;     // b*T + t
    const int h  = blockIdx.x & 7;
    const int hc = h * cHD;
    const size_t inBase = (size_t)bt * cN * cD;

    // Weight slices (rows hc..hc+15), Wm, biases
    for (int idx = tid; idx < 3 * 16 * 128; idx += 256) {
        const int m = idx / (16 * 128);
        const int rem = idx - m * 16 * 128;
        const int r = rem >> 7, c = rem & 127;
        const float* W = (m == 0) ? Wq : (m == 1) ? Wk : Wv;
        sW[m * (16 * W_ST) + r * W_ST + c] = W[(hc + r) * cD + c];
    }
    for (int idx = tid; idx < 16 * 64; idx += 256) sWM[idx] = Wm[idx];
    if (tid < 16) {
        sB[tid]      = bq[hc + tid];
        sB[16 + tid] = bk[hc + tid];
        sB[32 + tid] = bv[hc + tid];
        sB[48 + tid] = bm[tid];
    }

    // Stage input slice + project, for q, k, v in turn (sS doubles as staging buffer)
#pragma unroll 1
    for (int m = 0; m < 3; m++) {
        __syncthreads();   // also covers weight/bias loads on first iteration
        const float* gin = (m == 0) ? gq : (m == 1) ? gk : gv;
        for (int idx = tid; idx < cN * cD; idx += 256)
            sS[(idx >> 7) * IN_ST + (idx & 127)] = gin[inBase + idx];
        __syncthreads();
        const float* w = sW + m * (16 * W_ST);
        float* o = (m == 0) ? sQ : (m == 1) ? sK : sV;
        for (int idx = tid; idx < cN * cHD; idx += 256) {
            const int n = idx >> 4, r = idx & 15;
            float acc = sB[m * 16 + r];
            const float4* inrow = (const float4*)(sS + n * IN_ST);
            const float4* wrow  = (const float4*)(w + r * W_ST);
#pragma unroll 8
            for (int c4 = 0; c4 < 32; c4++) {
                float4 a = inrow[c4], bw = wrow[c4];
                acc += a.x * bw.x + a.y * bw.y + a.z * bw.z + a.w * bw.w;
            }
            o[n * V_ST + r] = acc;
        }
    }
    __syncthreads();

    // S = q k^T * 0.25
    for (int idx = tid; idx < cN * cN; idx += 256) {
        const int i = idx / cN, j = idx - i * cN;
        const float4* qr = (const float4*)(sQ + i * V_ST);
        const float4* kr = (const float4*)(sK + j * V_ST);
        float acc = 0.f;
#pragma unroll
        for (int f4 = 0; f4 < 4; f4++) {
            float4 a = qr[f4], b = kr[f4];
            acc += a.x * b.x + a.y * b.y + a.z * b.z + a.w * b.w;
        }
        sS[i * S_ST + j] = acc * 0.25f;
    }
    __syncthreads();

    // Row / column maxima
    if (tid < cN) {
        float m1 = -1e30f, m2 = -1e30f;
        for (int j = 0; j < cN; j++) {
            m1 = fmaxf(m1, sS[tid * S_ST + j]);
            m2 = fmaxf(m2, sS[j * S_ST + tid]);
        }
        sRM[tid] = m1;
        sCM[tid] = m2;
    }
    __syncthreads();

    // o1 (row softmax @ v) and o2 (col-softmax^T @ v), folded through Wm
    if (tid < cN) {
        const int i = tid;
        float acc[cHD];

        // o1
#pragma unroll
        for (int f = 0; f < cHD; f++) acc[f] = 0.f;
        float rs = 0.f;
        const float rm = sRM[i];
        for (int j = 0; j < cN; j++) {
            const float e = __expf(sS[i * S_ST + j] - rm);
            rs += e;
            const float4* vr = (const float4*)(sV + j * V_ST);
#pragma unroll
            for (int f4 = 0; f4 < 4; f4++) {
                float4 v4 = vr[f4];
                acc[4 * f4 + 0] += e * v4.x; acc[4 * f4 + 1] += e * v4.y;
                acc[4 * f4 + 2] += e * v4.z; acc[4 * f4 + 3] += e * v4.w;
            }
        }
        float inv = 1.f / rs;
#pragma unroll
        for (int f = 0; f < cHD; f++) acc[f] *= inv;
        fold_wm(acc, sWM, 0, sO, i, true, sB + 48);

        // o2
#pragma unroll
        for (int f = 0; f < cHD; f++) acc[f] = 0.f;
        float cs = 0.f;
        const float cmx = sCM[i];
        for (int j = 0; j < cN; j++) {
            const float e = __expf(sS[j * S_ST + i] - cmx);
            cs += e;
            const float4* vr = (const float4*)(sV + j * V_ST);
#pragma unroll
            for (int f4 = 0; f4 < 4; f4++) {
                float4 v4 = vr[f4];
                acc[4 * f4 + 0] += e * v4.x; acc[4 * f4 + 1] += e * v4.y;
                acc[4 * f4 + 2] += e * v4.z; acc[4 * f4 + 3] += e * v4.w;
            }
        }
        inv = 1.f / cs;
#pragma unroll
        for (int f = 0; f < cHD; f++) acc[f] *= inv;
        fold_wm(acc, sWM, 16, sO, i, false, sB + 48);
    }
    __syncthreads();

    // o3: adp_row @ v (stage adp_row into the free S buffer)
    for (int idx = tid; idx < cN * cN; idx += 256) {
        const int i = idx / cN, j = idx - i * cN;
        sS[i * S_ST + j] = gAdpRow[idx];
    }
    __syncthreads();
    if (tid < cN) {
        float acc[cHD];
        mat_row_dot(sS, sV, tid, acc);
        fold_wm(acc, sWM, 32, sO, tid, false, sB + 48);
    }
    __syncthreads();

    // o4: adp_col^T @ v
    for (int idx = tid; idx < cN * cN; idx += 256) {
        const int i = idx / cN, j = idx - i * cN;
        sS[i * S_ST + j] = gAdpColT[idx];
    }
    __syncthreads();
    if (tid < cN) {
        float acc[cHD];
        mat_row_dot(sS, sV, tid, acc);
        fold_wm(acc, sWM, 48, sO, tid, false, sB + 48);
    }
    __syncthreads();

    // write head-slice of intermediate [B,T,N,128]
    for (int idx = tid; idx < cN * cHD; idx += 256) {
        const int n = idx >> 4, j = idx & 15;
        gXmid[((size_t)bt * cN + n) * cD + hc + j] = sO[idx];
    }
}

// ---------------------------------------------------------------------------
// Final projection: d_out = Xmid @ Wo^T + bo
// ---------------------------------------------------------------------------
__global__ void __launch_bounds__(256)
out_proj_kernel(const float* __restrict__ Wo, const float* __restrict__ bo,
                float* __restrict__ out)
{
    extern __shared__ float sm[];
    float* sWo = sm;                  // 128 x 133
    float* sX  = sWo + 128 * 133;     // 32 x 133
    float* sBo = sX + 32 * 133;       // 128

    const int tid = threadIdx.x;
    for (int idx = tid; idx < 128 * 128; idx += 256) {
        const int c = idx >> 7, k = idx & 127;
        sWo[c * 133 + k] = Wo[idx];
    }
    if (tid < 128) sBo[tid] = bo[tid];
    const int row0 = blockIdx.x * 32;
    for (int idx = tid; idx < 32 * 128; idx += 256) {
        const int r = idx >> 7, k = idx & 127;
        sX[r * 133 + k] = gXmid[(size_t)(row0 + r) * cD + k];
    }
    __syncthreads();

    const int c  = tid & 127;
    const int rg = tid >> 7;          // 0..1 -> rows rg*16 .. rg*16+15
    float acc[16];
#pragma unroll
    for (int rr = 0; rr < 16; rr++) acc[rr] = sBo[c];
    const float* wrow = sWo + c * 133;
    for (int k = 0; k < 128; k++) {
        const float w = wrow[k];
#pragma unroll
        for (int rr = 0; rr < 16; rr++)
            acc[rr] += w * sX[(rg * 16 + rr) * 133 + k];
    }
#pragma unroll
    for (int rr = 0; rr < 16; rr++)
        out[(size_t)(row0 + rg * 16 + rr) * cD + c] = acc[rr];
}

// ---------------------------------------------------------------------------
// Launch
// ---------------------------------------------------------------------------
extern "C" void kernel_launch(void* const* d_in, const int* in_sizes, int n_in,
                              void* d_out, int out_size)
{
    const float* query = (const float*)d_in[0];
    const float* key   = (const float*)d_in[1];
    const float* value = (const float*)d_in[2];
    const float* Wq = (const float*)d_in[3];
    const float* bq = (const float*)d_in[4];
    const float* Wk = (const float*)d_in[5];
    const float* bk = (const float*)d_in[6];
    const float* Wv = (const float*)d_in[7];
    const float* bv = (const float*)d_in[8];
    const float* Wm = (const float*)d_in[9];
    const float* bm = (const float*)d_in[10];
    const float* Wo = (const float*)d_in[11];
    const float* bo = (const float*)d_in[12];
    const float* ne1 = (const float*)d_in[13];
    const float* ne2 = (const float*)d_in[14];
    // d_in[15] = dim (always 2 for this problem instance)

    cudaFuncSetAttribute(fused_kernel, cudaFuncAttributeMaxDynamicSharedMemorySize,
                         FUSED_FLOATS * (int)sizeof(float));
    cudaFuncSetAttribute(out_proj_kernel, cudaFuncAttributeMaxDynamicSharedMemorySize,
                         PROJ_FLOATS * (int)sizeof(float));

    adp_row_kernel<<<cN, 256>>>(ne1, ne2);
    adp_col_kernel<<<cN, 256>>>();
    fused_kernel<<<cB * cT * cH, 256, FUSED_FLOATS * sizeof(float)>>>(
        query, key, value, Wq, bq, Wk, bk, Wv, bv, Wm, bm);
    out_proj_kernel<<<(cB * cT * cN) / 32, 256, PROJ_FLOATS * sizeof(float)>>>(
        Wo, bo, (float*)d_out);
}

// round 2
// speedup vs baseline: 1.0702x; 1.0702x over previous
#include <cuda_runtime.h>

// Problem constants
#define cB 16
#define cT 16
#define cN 184
#define cD 128
#define cH 8
#define cHD 16
#define cEMB 10

// Device scratch (allocation-free requirement -> __device__ globals)
static __device__ float gXmid[cB * cT * cN * cD];   // pre-Wo intermediate [B,T,N,128]
static __device__ float gAdpRaw[cN * cN];
static __device__ float gAdpRow[cN * cN];           // softmax(adp, axis=-1)
static __device__ float gAdpColT[cN * cN];          // [i][k] = softmax(adp, axis=0)[k][i]

// Shared memory layout (floats)
#define S_ST 188          // 184x188 score/E matrix: rows 16B-aligned, conflict-free both ways
#define X_ST 132          // staged input 184x132
#define KT_ST 193         // k transposed 16x193

#define OFF_S    0
#define OFF_Q    34592            // 184*188
#define OFF_KT   38272            // +3680 (q: 184x20)
#define OFF_V    41360            // +3088 (kT: 16*193)
#define OFF_V1   44304            // +2944 (v: 184x16)
#define OFF_V2   47248
#define OFF_V3   50192
#define OFF_V4   OFF_Q            // reuse q slot (q dead after S-phase)
#define OFF_W    OFF_V1           // 3*16*132=6336 overlays V1..V3 (dead before v-fold)
#define OFF_WM   53136            // 16*64
#define OFF_BIAS 54160            // bq,bk,bv,bm slices (16 each)
#define OFF_RS   54224
#define OFF_CS   54408
#define OFF_RED  54592
#define FUSED_FLOATS 54624        // 218,496 bytes

// ---------------------------------------------------------------------------
// adp = ne1 @ ne2 ; row softmax
// ---------------------------------------------------------------------------
__global__ void adp_row_kernel(const float* __restrict__ ne1,
                               const float* __restrict__ ne2)
{
    __shared__ float red[256];
    const int i = blockIdx.x;
    const int j = threadIdx.x;

    float val = -1e30f;
    if (j < cN) {
        float acc = 0.f;
#pragma unroll
        for (int e = 0; e < cEMB; e++) acc += ne1[i * cEMB + e] * ne2[e * cN + j];
        val = acc;
        gAdpRaw[i * cN + j] = acc;
    }
    red[j] = val;
    __syncthreads();
    for (int s = 128; s > 0; s >>= 1) {
        if (j < s) red[j] = fmaxf(red[j], red[j + s]);
        __syncthreads();
    }
    const float m = red[0];
    __syncthreads();
    const float e = (j < cN) ? __expf(val - m) : 0.f;
    red[j] = e;
    __syncthreads();
    for (int s = 128; s > 0; s >>= 1) {
        if (j < s) red[j] += red[j + s];
        __syncthreads();
    }
    const float inv = 1.f / red[0];
    if (j < cN) gAdpRow[i * cN + j] = e * inv;
}

__global__ void adp_col_kernel()
{
    __shared__ float red[256];
    const int i = blockIdx.x;       // column of adp
    const int k = threadIdx.x;

    float val = -1e30f;
    if (k < cN) val = gAdpRaw[k * cN + i];
    red[k] = val;
    __syncthreads();
    for (int s = 128; s > 0; s >>= 1) {
        if (k < s) red[k] = fmaxf(red[k], red[k + s]);
        __syncthreads();
    }
    const float m = red[0];
    __syncthreads();
    const float e = (k < cN) ? __expf(val - m) : 0.f;
    red[k] = e;
    __syncthreads();
    for (int s = 128; s > 0; s >>= 1) {
        if (k < s) red[k] += red[k + s];
        __syncthreads();
    }
    const float inv = 1.f / red[0];
    if (k < cN) gAdpColT[i * cN + k] = e * inv;
}

__device__ __forceinline__ float dot4(float4 a, float4 b) {
    return a.x * b.x + a.y * b.y + a.z * b.z + a.w * b.w;
}
__device__ __forceinline__ void fma4(float4& acc, float s, float4 v) {
    acc.x += s * v.x; acc.y += s * v.y; acc.z += s * v.z; acc.w += s * v.w;
}

// ---------------------------------------------------------------------------
// Fused per-(b,t,h): QKV proj + dual-softmax (single E) + adp mixes, Wm pre-folded
// 736 threads: thread = (i in 0..183, q in 0..3)
// ---------------------------------------------------------------------------
__global__ void __launch_bounds__(736, 1)
fused_kernel(const float* __restrict__ gq, const float* __restrict__ gk,
             const float* __restrict__ gv,
             const float* __restrict__ Wq, const float* __restrict__ bq,
             const float* __restrict__ Wk, const float* __restrict__ bk,
             const float* __restrict__ Wv, const float* __restrict__ bv,
             const float* __restrict__ Wm, const float* __restrict__ bm)
{
    extern __shared__ float sm[];
    float* sS  = sm + OFF_S;
    float* sQ  = sm + OFF_Q;
    float* sKT = sm + OFF_KT;
    float* sV  = sm + OFF_V;
    float* sV1 = sm + OFF_V1;
    float* sV2 = sm + OFF_V2;
    float* sV3 = sm + OFF_V3;
    float* sV4 = sm + OFF_V4;
    float* sW  = sm + OFF_W;
    float* sWM = sm + OFF_WM;
    float* sB  = sm + OFF_BIAS;
    float* sRS = sm + OFF_RS;
    float* sCS = sm + OFF_CS;
    float* sRED = sm + OFF_RED;

    const int tid = threadIdx.x;
    const int bt  = blockIdx.x >> 3;
    const int h   = blockIdx.x & 7;
    const int hc  = h * cHD;
    const size_t inBase = (size_t)bt * cN * cD;

    const int i  = tid >> 2;     // row 0..183
    const int qq = tid & 3;      // quarter
    const int f0 = qq * 4;
    const int j0 = qq * 46;

    // Weight slices (rows hc..hc+15) + Wm + biases
    for (int idx = tid; idx < 3 * 16 * 128; idx += 736) {
        const int m = idx >> 11;
        const int rem = idx & 2047;
        const int r = rem >> 7, c = rem & 127;
        const float* W = (m == 0) ? Wq : (m == 1) ? Wk : Wv;
        sW[(m * 16 + r) * X_ST + c] = W[(hc + r) * cD + c];
    }
    for (int idx = tid; idx < 16 * 64; idx += 736) sWM[idx] = Wm[idx];
    if (tid < 16) {
        sB[tid]      = bq[hc + tid];
        sB[16 + tid] = bk[hc + tid];
        sB[32 + tid] = bv[hc + tid];
        sB[48 + tid] = bm[tid];
    }

    // ---- projections: stage X into sS, 4 outputs per thread ----
#pragma unroll 1
    for (int m = 0; m < 3; m++) {
        __syncthreads();   // protects sS reuse + first-iter weight loads
        const float* gin = (m == 0) ? gq : (m == 1) ? gk : gv;
        for (int idx = tid; idx < (cN * cD) / 4; idx += 736) {
            const int r = idx >> 5, c4 = idx & 31;
            *(float4*)&sS[r * X_ST + c4 * 4] = *(const float4*)&gin[inBase + r * cD + c4 * 4];
        }
        __syncthreads();

        float a0 = sB[m * 16 + f0], a1 = sB[m * 16 + f0 + 1];
        float a2 = sB[m * 16 + f0 + 2], a3 = sB[m * 16 + f0 + 3];
        const float* xrow = &sS[i * X_ST];
        const float* w0 = &sW[(m * 16 + f0) * X_ST];
#pragma unroll 4
        for (int c4 = 0; c4 < 32; c4++) {
            const float4 x4 = *(const float4*)&xrow[c4 * 4];
            a0 += dot4(x4, *(const float4*)&w0[0 * X_ST + c4 * 4]);
            a1 += dot4(x4, *(const float4*)&w0[1 * X_ST + c4 * 4]);
            a2 += dot4(x4, *(const float4*)&w0[2 * X_ST + c4 * 4]);
            a3 += dot4(x4, *(const float4*)&w0[3 * X_ST + c4 * 4]);
        }
        if (m == 0) {            // fold 1/sqrt(HD)=0.25 into q
            sQ[i * 20 + f0 + 0] = a0 * 0.25f; sQ[i * 20 + f0 + 1] = a1 * 0.25f;
            sQ[i * 20 + f0 + 2] = a2 * 0.25f; sQ[i * 20 + f0 + 3] = a3 * 0.25f;
        } else if (m == 1) {     // k transposed
            sKT[(f0 + 0) * KT_ST + i] = a0; sKT[(f0 + 1) * KT_ST + i] = a1;
            sKT[(f0 + 2) * KT_ST + i] = a2; sKT[(f0 + 3) * KT_ST + i] = a3;
        } else {
            sV[i * 16 + f0 + 0] = a0; sV[i * 16 + f0 + 1] = a1;
            sV[i * 16 + f0 + 2] = a2; sV[i * 16 + f0 + 3] = a3;
        }
    }
    __syncthreads();

    // ---- combined phase: v1..v3 = v @ Wm_g^T  AND  S = q k^T ----
    {
        const float4 va = *(const float4*)&sV[i * 16 + 0];
        const float4 vb = *(const float4*)&sV[i * 16 + 4];
        const float4 vc = *(const float4*)&sV[i * 16 + 8];
        const float4 vd = *(const float4*)&sV[i * 16 + 12];
#pragma unroll
        for (int g = 0; g < 3; g++) {
            float* dst = (g == 0) ? sV1 : (g == 1) ? sV2 : sV3;
#pragma unroll
            for (int j = 0; j < 4; j++) {
                const float* wr = &sWM[(f0 + j) * 64 + g * 16];
                float s = dot4(va, *(const float4*)&wr[0]) + dot4(vb, *(const float4*)&wr[4])
                        + dot4(vc, *(const float4*)&wr[8]) + dot4(vd, *(const float4*)&wr[12]);
                dst[i * 16 + f0 + j] = s;
            }
        }
        // S rows: this thread covers row i, columns j0..j0+45
        float qr[16];
        *(float4*)&qr[0]  = *(const float4*)&sQ[i * 20 + 0];
        *(float4*)&qr[4]  = *(const float4*)&sQ[i * 20 + 4];
        *(float4*)&qr[8]  = *(const float4*)&sQ[i * 20 + 8];
        *(float4*)&qr[12] = *(const float4*)&sQ[i * 20 + 12];
#pragma unroll 2
        for (int s = 0; s < 46; s++) {
            const int j = j0 + s;
            float acc = 0.f;
#pragma unroll
            for (int f = 0; f < 16; f++) acc += qr[f] * sKT[f * KT_ST + j];
            sS[i * S_ST + j] = acc;
        }
    }
    __syncthreads();

    // ---- block max (for shift) + v4 fold (q slot now dead) ----
    {
        float lmax = -1e30f;
        for (int s = 0; s < 46; s++) lmax = fmaxf(lmax, sS[i * S_ST + j0 + s]);
#pragma unroll
        for (int off = 16; off; off >>= 1)
            lmax = fmaxf(lmax, __shfl_xor_sync(0xffffffffu, lmax, off));
        if ((tid & 31) == 0) sRED[tid >> 5] = lmax;

        const float4 va = *(const float4*)&sV[i * 16 + 0];
        const float4 vb = *(const float4*)&sV[i * 16 + 4];
        const float4 vc = *(const float4*)&sV[i * 16 + 8];
        const float4 vd = *(const float4*)&sV[i * 16 + 12];
#pragma unroll
        for (int j = 0; j < 4; j++) {
            const float* wr = &sWM[(f0 + j) * 64 + 48];
            float s = dot4(va, *(const float4*)&wr[0]) + dot4(vb, *(const float4*)&wr[4])
                    + dot4(vc, *(const float4*)&wr[8]) + dot4(vd, *(const float4*)&wr[12]);
            sV4[i * 16 + f0 + j] = s;
        }
    }
    __syncthreads();
    float M = sRED[0];
#pragma unroll
    for (int w = 1; w < 23; w++) M = fmaxf(M, sRED[w]);

    // ---- E = exp(S - M) in place, row sums ----
    {
        float part = 0.f;
#pragma unroll 2
        for (int s = 0; s < 46; s++) {
            const float e = __expf(sS[i * S_ST + j0 + s] - M);
            sS[i * S_ST + j0 + s] = e;
            part += e;
        }
        part += __shfl_xor_sync(0xffffffffu, part, 1);
        part += __shfl_xor_sync(0xffffffffu, part, 2);
        if (qq == 0) sRS[i] = part;
    }
    __syncthreads();
    // ---- column sums ----
    {
        float part = 0.f;
#pragma unroll 2
        for (int s = 0; s < 46; s++) part += sS[(j0 + s) * S_ST + i];
        part += __shfl_xor_sync(0xffffffffu, part, 1);
        part += __shfl_xor_sync(0xffffffffu, part, 2);
        if (qq == 0) sCS[i] = part;
    }
    __syncthreads();

    // ---- four accumulated GEMMs: out_i = E_i./rs @ v1 + (E_.i/cs) @ v2 + R_i. @ v3 + CT_i. @ v4 ----
    {
        float4 A1 = make_float4(0.f, 0.f, 0.f, 0.f);
        float4 A2 = make_float4(0.f, 0.f, 0.f, 0.f);
        float4 A34 = make_float4(0.f, 0.f, 0.f, 0.f);

        const float* Rrow = &gAdpRow[i * cN];
        const float* Crow = &gAdpColT[i * cN];
        float4 r4 = __ldg((const float4*)&Rrow[0]);
        float4 c4 = __ldg((const float4*)&Crow[0]);

#pragma unroll 1
        for (int kk = 0; kk < cN; kk += 4) {
            const float4 er = *(const float4*)&sS[i * S_ST + kk];
            const float ec0 = sS[(kk + 0) * S_ST + i];
            const float ec1 = sS[(kk + 1) * S_ST + i];
            const float ec2 = sS[(kk + 2) * S_ST + i];
            const float ec3 = sS[(kk + 3) * S_ST + i];

            float4 rn = r4, cn = c4;
            if (kk + 4 < cN) {
                rn = __ldg((const float4*)&Rrow[kk + 4]);
                cn = __ldg((const float4*)&Crow[kk + 4]);
            }

            fma4(A1, er.x, *(const float4*)&sV1[(kk + 0) * 16 + f0]);
            fma4(A1, er.y, *(const float4*)&sV1[(kk + 1) * 16 + f0]);
            fma4(A1, er.z, *(const float4*)&sV1[(kk + 2) * 16 + f0]);
            fma4(A1, er.w, *(const float4*)&sV1[(kk + 3) * 16 + f0]);

            fma4(A2, ec0, *(const float4*)&sV2[(kk + 0) * 16 + f0]);
            fma4(A2, ec1, *(const float4*)&sV2[(kk + 1) * 16 + f0]);
            fma4(A2, ec2, *(const float4*)&sV2[(kk + 2) * 16 + f0]);
            fma4(A2, ec3, *(const float4*)&sV2[(kk + 3) * 16 + f0]);

            fma4(A34, r4.x, *(const float4*)&sV3[(kk + 0) * 16 + f0]);
            fma4(A34, r4.y, *(const float4*)&sV3[(kk + 1) * 16 + f0]);
            fma4(A34, r4.z, *(const float4*)&sV3[(kk + 2) * 16 + f0]);
            fma4(A34, r4.w, *(const float4*)&sV3[(kk + 3) * 16 + f0]);

            fma4(A34, c4.x, *(const float4*)&sV4[(kk + 0) * 16 + f0]);
            fma4(A34, c4.y, *(const float4*)&sV4[(kk + 1) * 16 + f0]);
            fma4(A34, c4.z, *(const float4*)&sV4[(kk + 2) * 16 + f0]);
            fma4(A34, c4.w, *(const float4*)&sV4[(kk + 3) * 16 + f0]);

            r4 = rn; c4 = cn;
        }

        const float invr = 1.f / sRS[i];
        const float invc = 1.f / sCS[i];
        float4 o;
        o.x = A1.x * invr + A2.x * invc + A34.x + sB[48 + f0 + 0];
        o.y = A1.y * invr + A2.y * invc + A34.y + sB[48 + f0 + 1];
        o.z = A1.z * invr + A2.z * invc + A34.z + sB[48 + f0 + 2];
        o.w = A1.w * invr + A2.w * invc + A34.w + sB[48 + f0 + 3];
        *(float4*)&gXmid[((size_t)bt * cN + i) * cD + hc + f0] = o;
    }
}

// ---------------------------------------------------------------------------
// Final projection: d_out = Xmid @ Wo^T + bo  — 64x64 tiles, 4x4 per thread
// ---------------------------------------------------------------------------
#define OP_ST 132
#define PROJ_FLOATS (2 * 64 * OP_ST)   // 16896 floats = 67584 bytes

__global__ void __launch_bounds__(256)
out_proj_kernel(const float* __restrict__ Wo, const float* __restrict__ bo,
                float* __restrict__ out)
{
    extern __shared__ float sm[];
    float* sX = sm;                  // 64 x 132
    float* sWt = sm + 64 * OP_ST;    // 64 x 132

    const int tid = threadIdx.x;
    const int row0 = blockIdx.x * 64;
    const int cb = blockIdx.y * 64;

    for (int idx = tid; idx < 64 * 32; idx += 256) {
        const int r = idx >> 5, c4 = idx & 31;
        *(float4*)&sX[r * OP_ST + c4 * 4] =
            *(const float4*)&gXmid[(size_t)(row0 + r) * cD + c4 * 4];
        *(float4*)&sWt[r * OP_ST + c4 * 4] =
            *(const float4*)&Wo[(size_t)(cb + r) * cD + c4 * 4];
    }
    __syncthreads();

    const int tx = tid & 15, ty = tid >> 4;
    const int r0 = ty * 4, c0 = tx * 4;

    float acc[4][4];
#pragma unroll
    for (int a = 0; a < 4; a++)
#pragma unroll
        for (int b = 0; b < 4; b++) acc[a][b] = 0.f;

#pragma unroll 2
    for (int k4 = 0; k4 < 32; k4++) {
        float4 xa[4], wb[4];
#pragma unroll
        for (int j = 0; j < 4; j++) {
            xa[j] = *(const float4*)&sX[(r0 + j) * OP_ST + k4 * 4];
            wb[j] = *(const float4*)&sWt[(c0 + j) * OP_ST + k4 * 4];
        }
#pragma unroll
        for (int a = 0; a < 4; a++)
#pragma unroll
            for (int b = 0; b < 4; b++) acc[a][b] += dot4(xa[a], wb[b]);
    }

    const float4 bo4 = __ldg((const float4*)&bo[cb + c0]);
#pragma unroll
    for (int a = 0; a < 4; a++) {
        float4 o;
        o.x = acc[a][0] + bo4.x; o.y = acc[a][1] + bo4.y;
        o.z = acc[a][2] + bo4.z; o.w = acc[a][3] + bo4.w;
        *(float4*)&out[(size_t)(row0 + r0 + a) * cD + cb + c0] = o;
    }
}

// ---------------------------------------------------------------------------
// Launch
// ---------------------------------------------------------------------------
extern "C" void kernel_launch(void* const* d_in, const int* in_sizes, int n_in,
                              void* d_out, int out_size)
{
    const float* query = (const float*)d_in[0];
    const float* key   = (const float*)d_in[1];
    const float* value = (const float*)d_in[2];
    const float* Wq = (const float*)d_in[3];
    const float* bq = (const float*)d_in[4];
    const float* Wk = (const float*)d_in[5];
    const float* bk = (const float*)d_in[6];
    const float* Wv = (const float*)d_in[7];
    const float* bv = (const float*)d_in[8];
    const float* Wm = (const float*)d_in[9];
    const float* bm = (const float*)d_in[10];
    const float* Wo = (const float*)d_in[11];
    const float* bo = (const float*)d_in[12];
    const float* ne1 = (const float*)d_in[13];
    const float* ne2 = (const float*)d_in[14];

    cudaFuncSetAttribute(fused_kernel, cudaFuncAttributeMaxDynamicSharedMemorySize,
                         FUSED_FLOATS * (int)sizeof(float));
    cudaFuncSetAttribute(out_proj_kernel, cudaFuncAttributeMaxDynamicSharedMemorySize,
                         PROJ_FLOATS * (int)sizeof(float));

    adp_row_kernel<<<cN, 256>>>(ne1, ne2);
    adp_col_kernel<<<cN, 256>>>();
    fused_kernel<<<cB * cT * cH, 736, FUSED_FLOATS * sizeof(float)>>>(
        query, key, value, Wq, bq, Wk, bk, Wv, bv, Wm, bm);
    dim3 pg((cB * cT * cN) / 64, 2);
    out_proj_kernel<<<pg, 256, PROJ_FLOATS * sizeof(float)>>>(Wo, bo, (float*)d_out);
}